// round 7
// baseline (speedup 1.0000x reference)
#include <cuda_runtime.h>
#include <math.h>

// Problem constants
#define BB    128
#define TT    2048
#define DIN   32
#define HH    256
#define G4    1024          // 4*H
#define KK    288           // H + DIN (input projection folded into recurrence)
#define NBLK  128           // 8 group-pairs x 16 column-slices (1/SM, co-resident)
#define MPB   8             // batch rows per group
#define NPB   16            // h-cols per block slice
#define JPB   64            // gate cols per block = 4*NPB
#define NGRP  16            // batch groups (8 pairs x 2)

// -------- static device scratch (no allocation allowed) --------
__device__ float    g_Wcomb[G4 * DIN];      // W_ih @ W_in   [1024][32]
__device__ float    g_bias[G4];             // b_ih + b_hh + W_ih @ b_in
__device__ float    g_h[2][BB][HH];         // double-buffered LSTM hidden state
__device__ float    g_emaA[BB * 32 * HH];
__device__ float    g_emaP[BB * 32 * HH];
__device__ float    g_ema_last[BB * HH];
__device__ unsigned g_cnt[NGRP * 32];       // per-group arrival counters (128B apart)

// ---------------- asm / math helpers -----------------------------------------
__device__ __forceinline__ unsigned ld_acq(const unsigned* p) {
    unsigned v;
    asm volatile("ld.acquire.gpu.global.u32 %0, [%1];" : "=r"(v) : "l"(p));
    return v;
}
__device__ __forceinline__ void red_add_release(unsigned* p, unsigned v) {
    asm volatile("red.release.gpu.global.add.u32 [%0], %1;" :: "l"(p), "r"(v) : "memory");
}
__device__ __forceinline__ float fsig(float x) {          // fast sigmoid
    return __fdividef(1.0f, 1.0f + __expf(-x));
}
__device__ __forceinline__ float ftanh(float x) {         // fast tanh
    return 1.0f - __fdividef(2.0f, __expf(2.0f * x) + 1.0f);
}
__device__ __forceinline__ unsigned long long dup2(float a) {
    unsigned long long r;
    asm("mov.b64 %0, {%1, %1};" : "=l"(r) : "f"(a));
    return r;
}
__device__ __forceinline__ void ffma2(unsigned long long& d,
                                      unsigned long long a, unsigned long long b) {
    asm("fma.rn.f32x2 %0, %1, %2, %0;" : "+l"(d) : "l"(a), "l"(b));
}
__device__ __forceinline__ void unpk(unsigned long long v, float& lo, float& hi) {
    asm("mov.b64 {%0, %1}, %2;" : "=f"(lo), "=f"(hi) : "l"(v));
}

// ---------------- prep: W_comb, fused bias, zero h(0), zero counters ---------
__global__ void __launch_bounds__(256)
prep_kernel(const float* __restrict__ W_in, const float* __restrict__ b_in,
            const float* __restrict__ W_ih, const float* __restrict__ b_ih,
            const float* __restrict__ b_hh)
{
    int idx = blockIdx.x * 256 + threadIdx.x;
    if (idx < NGRP * 32) g_cnt[idx] = 0u;
    if (idx < G4 * DIN) {
        int r = idx >> 5;          // gate row 0..1023
        int c = idx & 31;          // input col 0..31
        float s = 0.0f;
        for (int k = 0; k < HH; k++)
            s = fmaf(W_ih[r * HH + k], W_in[k * DIN + c], s);
        g_Wcomb[idx] = s;
        ((float*)g_h)[idx] = 0.0f;             // zero buffer 0 = h(0) (same 32768 extent)
    } else if (idx < G4 * DIN + G4) {
        int r = idx - G4 * DIN;
        float s = b_ih[r] + b_hh[r];
        for (int k = 0; k < HH; k++)
            s = fmaf(W_ih[r * HH + k], b_in[k], s);
        g_bias[r] = s;
    }
}

// ---------------- EMA: 64-step chunk -> (A, P) with out = A + P*prev ---------
__global__ void __launch_bounds__(256)
ema_scan_kernel(const float* __restrict__ x,
                const float* __restrict__ W_proj, const float* __restrict__ b_proj,
                const float* __restrict__ W_gate, const float* __restrict__ b_gate)
{
    const int b  = blockIdx.x >> 5;
    const int ch = blockIdx.x & 31;
    const int h  = threadIdx.x;

    __shared__ __align__(16) float x_s[64][DIN];
    for (int i = h; i < 64 * DIN; i += 256) {
        int tt = i >> 5, kk = i & 31;
        x_s[tt][kk] = x[((size_t)b * TT + ch * 64 + tt) * DIN + kk];
    }
    float wz[DIN], wg[DIN];
#pragma unroll
    for (int k = 0; k < DIN; k++) {
        wz[k] = W_proj[h * DIN + k];
        wg[k] = W_gate[h * DIN + k];
    }
    const float bz = b_proj[h], bgv = b_gate[h];
    __syncthreads();

    float A = 0.0f, P = 1.0f;
    for (int tt = 0; tt < 64; tt++) {
        float z = bz, gp = bgv;
#pragma unroll
        for (int q = 0; q < 8; q++) {
            float4 xq = *(const float4*)&x_s[tt][q * 4];
            z  = fmaf(wz[q*4+0], xq.x, z);  z  = fmaf(wz[q*4+1], xq.y, z);
            z  = fmaf(wz[q*4+2], xq.z, z);  z  = fmaf(wz[q*4+3], xq.w, z);
            gp = fmaf(wg[q*4+0], xq.x, gp); gp = fmaf(wg[q*4+1], xq.y, gp);
            gp = fmaf(wg[q*4+2], xq.z, gp); gp = fmaf(wg[q*4+3], xq.w, gp);
        }
        float g  = fsig(gp);
        float om = 1.0f - g;
        A = fmaf(om, A, g * z);
        P *= om;
    }
    g_emaA[((size_t)b * 32 + ch) * HH + h] = A;
    g_emaP[((size_t)b * 32 + ch) * HH + h] = P;
}

__global__ void __launch_bounds__(256) ema_combine_kernel()
{
    const int b = blockIdx.x;
    const int h = threadIdx.x;
    float prev = 0.0f;
#pragma unroll 8
    for (int c = 0; c < 32; c++) {
        float A = g_emaA[((size_t)b * 32 + c) * HH + h];
        float P = g_emaP[((size_t)b * 32 + c) * HH + h];
        prev = fmaf(P, prev, A);
    }
    g_ema_last[b * HH + h] = prev;
}

// ---------------- persistent LSTM recurrence --------------------------------
// 128 blocks = 8 group-pairs x 16 col-slices. Each block alternates the two
// independent groups of its pair (A = rows m0A..+7, B = m0A+8..+15) so each
// group's barrier/L2 latency hides under the other group's compute.
// Column order inside block: j = hc*4 + gi (gate-major-last) so the gate
// reduction reads float4.
// SMEM: W_s[288][64], h_s[288][8], red_s[8][8][64], bias_s[64].
#define SMEM_FLOATS (KK*JPB + KK*MPB + 8*MPB*JPB + JPB)
#define SMEM_BYTES  (SMEM_FLOATS * 4)

__global__ void __launch_bounds__(256, 1)
recur_kernel(const float* __restrict__ x, const float* __restrict__ W_hh)
{
    extern __shared__ float sm[];
    float* W_s    = sm;                        // [288][64]
    float* h_s    = W_s + KK * JPB;            // [288][8]
    float* red_s  = h_s + KK * MPB;            // [8][8][64]
    float* bias_s = red_s + 8 * MPB * JPB;     // [64]

    const int tid   = threadIdx.x;
    const int pair  = blockIdx.x >> 4;         // 0..7
    const int slice = blockIdx.x & 15;         // 0..15
    const int n0    = slice * NPB;
    const int m0A   = pair * 16;
    const int m0B   = m0A + 8;

    // one-time: stage weight slice, col j = hc*4+gi -> gate row r = gi*256+n0+hc
    for (int idx = tid; idx < KK * JPB; idx += 256) {
        int k = idx >> 6;
        int j = idx & 63;
        int r = ((j & 3) << 8) + n0 + (j >> 2);
        W_s[idx] = (k < HH) ? W_hh[r * HH + k] : g_Wcomb[r * DIN + (k - HH)];
    }
    if (tid < JPB)
        bias_s[tid] = g_bias[((tid & 3) << 8) + n0 + (tid >> 2)];
    __syncthreads();

    const int w     = tid >> 5;      // warp id = staging batch row / k-split id
    const int lane  = tid & 31;
    const int kbase = w * 36;        // 8 warps * 36 = 288 = K
    const int mg    = tid >> 4;      // gate-phase batch row (tid<128)
    const int hcg   = tid & 15;      // gate-phase h-col
    float cA = 0.0f, cB = 0.0f;
    float4 bv = make_float4(0.f, 0.f, 0.f, 0.f);
    if (tid < 128) bv = *(const float4*)&bias_s[hcg * 4];

    unsigned* cntA = &g_cnt[(2 * pair) * 32];
    unsigned* cntB = &g_cnt[(2 * pair + 1) * 32];

#define PHASE(m0G, cntG, cG)                                                   \
    {                                                                          \
        const float xv = __ldg(&x[((size_t)(m0G + w) * TT + t) * DIN + lane]); \
        if (tid == 0 && t > 0) {                                               \
            const unsigned tgt = 16u * (unsigned)t;                            \
            while (ld_acq(cntG) < tgt) { }                                     \
        }                                                                      \
        __syncthreads();                                                       \
        {   /* stage h(t) row m0G+w from L2, plus x_t */                       \
            const float* hb = &g_h[p][m0G + w][0];                             \
            _Pragma("unroll")                                                  \
            for (int q = 0; q < 8; q++)                                        \
                h_s[(lane + 32 * q) * MPB + w] = __ldcg(&hb[lane + 32 * q]);   \
            h_s[(HH + lane) * MPB + w] = xv;                                   \
        }                                                                      \
        __syncthreads();                                                       \
        {   /* K-split matvec, f32x2 over batch-row pairs */                   \
            unsigned long long acc2[4][2];                                     \
            _Pragma("unroll")                                                  \
            for (int mp = 0; mp < 4; mp++) { acc2[mp][0] = 0ull; acc2[mp][1] = 0ull; } \
            _Pragma("unroll 6")                                                \
            for (int kk = 0; kk < 36; kk++) {                                  \
                const int k = kbase + kk;                                      \
                const ulonglong2 hA4 = *(const ulonglong2*)&h_s[k * MPB + 0];  \
                const ulonglong2 hB4 = *(const ulonglong2*)&h_s[k * MPB + 4];  \
                const unsigned long long hp[4] = { hA4.x, hA4.y, hB4.x, hB4.y };\
                const float2 wv = *(const float2*)&W_s[k * JPB + 2 * lane];    \
                const unsigned long long w0 = dup2(wv.x), w1 = dup2(wv.y);     \
                _Pragma("unroll")                                              \
                for (int mp = 0; mp < 4; mp++) {                               \
                    ffma2(acc2[mp][0], hp[mp], w0);                            \
                    ffma2(acc2[mp][1], hp[mp], w1);                            \
                }                                                              \
            }                                                                  \
            _Pragma("unroll")                                                  \
            for (int mp = 0; mp < 4; mp++) {                                   \
                float l0, h0, l1, h1;                                          \
                unpk(acc2[mp][0], l0, h0);                                     \
                unpk(acc2[mp][1], l1, h1);                                     \
                *(float2*)&red_s[(w * MPB + 2 * mp) * JPB + 2 * lane] =        \
                    make_float2(l0, l1);                                       \
                *(float2*)&red_s[(w * MPB + 2 * mp + 1) * JPB + 2 * lane] =    \
                    make_float2(h0, h1);                                       \
            }                                                                  \
        }                                                                      \
        __syncthreads();                                                       \
        if (tid < 128) {  /* gate phase: float4 reduction over 8 k-partials */ \
            float4 sv = bv;                                                    \
            _Pragma("unroll")                                                  \
            for (int tk = 0; tk < 8; tk++) {                                   \
                const float4 r4 =                                              \
                    *(const float4*)&red_s[(tk * MPB + mg) * JPB + hcg * 4];   \
                sv.x += r4.x; sv.y += r4.y; sv.z += r4.z; sv.w += r4.w;        \
            }                                                                  \
            const float ig = fsig(sv.x);                                       \
            const float fg = fsig(sv.y);                                       \
            const float gg = ftanh(sv.z);                                      \
            const float og = fsig(sv.w);                                       \
            cG = fmaf(fg, cG, ig * gg);                                        \
            g_h[p ^ 1][m0G + mg][n0 + hcg] = og * ftanh(cG);                   \
        }                                                                      \
        __syncthreads();                                                       \
        if (tid == 0) red_add_release(cntG, 1u);                               \
    }

    for (int t = 0; t < TT; t++) {
        const int p = t & 1;
        PHASE(m0A, cntA, cA)
        PHASE(m0B, cntB, cB)
    }
#undef PHASE
    // h_last = h(2048) lives in g_h[0]
}

// ---------------- head: concat -> LayerNorm -> GELU(erf) MLP -> out ---------
__global__ void __launch_bounds__(256)
head_kernel(const float* __restrict__ ln_scale, const float* __restrict__ ln_bias,
            const float* __restrict__ W_h1, const float* __restrict__ b_h1,
            const float* __restrict__ W_h2, const float* __restrict__ b_h2,
            float* __restrict__ out)
{
    __shared__ __align__(16) float ns[512];
    __shared__ float red[32];
    __shared__ float mu_s, rv_s;

    const int b = blockIdx.x;
    const int tid = threadIdx.x;

    const float v0 = g_h[0][b][tid];
    const float v1 = g_ema_last[b * HH + tid];

    float s = v0 + v1, sq = v0 * v0 + v1 * v1;
#pragma unroll
    for (int o = 16; o; o >>= 1) {
        s  += __shfl_down_sync(0xffffffffu, s,  o);
        sq += __shfl_down_sync(0xffffffffu, sq, o);
    }
    if ((tid & 31) == 0) { red[tid >> 5] = s; red[8 + (tid >> 5)] = sq; }
    __syncthreads();
    if (tid == 0) {
        float ts = 0.f, tq = 0.f;
        for (int i = 0; i < 8; i++) { ts += red[i]; tq += red[8 + i]; }
        float mu = ts / 512.0f;
        mu_s = mu;
        rv_s = rsqrtf(tq / 512.0f - mu * mu + 1e-5f);
    }
    __syncthreads();
    const float mu = mu_s, ri = rv_s;
    ns[tid]       = fmaf((v0 - mu) * ri, ln_scale[tid],       ln_bias[tid]);
    ns[tid + 256] = fmaf((v1 - mu) * ri, ln_scale[tid + 256], ln_bias[tid + 256]);
    __syncthreads();

    float acc = b_h1[tid];
    const float4* wr = (const float4*)(W_h1 + (size_t)tid * 512);
#pragma unroll 8
    for (int q = 0; q < 128; q++) {
        float4 w = wr[q];
        float4 n = *(const float4*)&ns[q * 4];
        acc = fmaf(w.x, n.x, acc); acc = fmaf(w.y, n.y, acc);
        acc = fmaf(w.z, n.z, acc); acc = fmaf(w.w, n.w, acc);
    }
    float g1 = 0.5f * acc * (1.0f + erff(acc * 0.70710678118654752f));
    float p = g1 * W_h2[tid];
#pragma unroll
    for (int o = 16; o; o >>= 1) p += __shfl_down_sync(0xffffffffu, p, o);
    if ((tid & 31) == 0) red[16 + (tid >> 5)] = p;
    __syncthreads();
    if (tid == 0) {
        float tsum = b_h2[0];
        for (int i = 0; i < 8; i++) tsum += red[16 + i];
        out[b] = tsum;
    }
}

// ---------------- launch ----------------------------------------------------
extern "C" void kernel_launch(void* const* d_in, const int* in_sizes, int n_in,
                              void* d_out, int out_size)
{
    (void)in_sizes; (void)n_in; (void)out_size;
    const float* x        = (const float*)d_in[0];
    const float* W_in     = (const float*)d_in[1];
    const float* b_in     = (const float*)d_in[2];
    const float* W_ih     = (const float*)d_in[3];
    const float* W_hh     = (const float*)d_in[4];
    const float* b_ih     = (const float*)d_in[5];
    const float* b_hh     = (const float*)d_in[6];
    const float* W_proj   = (const float*)d_in[7];
    const float* b_proj   = (const float*)d_in[8];
    const float* W_gate   = (const float*)d_in[9];
    const float* b_gate   = (const float*)d_in[10];
    const float* ln_scale = (const float*)d_in[11];
    const float* ln_bias  = (const float*)d_in[12];
    const float* W_h1     = (const float*)d_in[13];
    const float* b_h1     = (const float*)d_in[14];
    const float* W_h2     = (const float*)d_in[15];
    const float* b_h2     = (const float*)d_in[16];
    float* out = (float*)d_out;

    cudaFuncSetAttribute(recur_kernel,
                         cudaFuncAttributeMaxDynamicSharedMemorySize, SMEM_BYTES);

    prep_kernel<<<132, 256>>>(W_in, b_in, W_ih, b_ih, b_hh);
    recur_kernel<<<NBLK, 256, SMEM_BYTES>>>(x, W_hh);
    ema_scan_kernel<<<BB * 32, 256>>>(x, W_proj, b_proj, W_gate, b_gate);
    ema_combine_kernel<<<BB, 256>>>();
    head_kernel<<<BB, 256>>>(ln_scale, ln_bias, W_h1, b_h1, W_h2, b_h2, out);
}

// round 8
// speedup vs baseline: 1.4148x; 1.4148x over previous
#include <cuda_runtime.h>
#include <math.h>

// Problem constants
#define BB    128
#define TT    2048
#define DIN   32
#define HH    256
#define G4    1024          // 4*H
#define KK    288           // H + DIN (input projection folded into recurrence)
#define NBLK  128           // persistent recurrence blocks (1/SM, co-resident)
#define MPB   8             // batch rows per block   (16 groups)
#define NPB   32            // h-cols per block       (8 slices)
#define JPB   128           // gate cols per block = 4*NPB
#define NGRP  16            // batch groups
#define HS    10            // h_s row stride (floats): 2-way-conflict, 8B-aligned pairs

// -------- static device scratch (no allocation allowed) --------
__device__ float    g_Wcomb[G4 * DIN];      // W_ih @ W_in   [1024][32]
__device__ float    g_bias[G4];             // b_ih + b_hh + W_ih @ b_in
__device__ float    g_h[2][BB][HH];         // double-buffered LSTM hidden state
__device__ float    g_emaA[BB * 32 * HH];
__device__ float    g_emaP[BB * 32 * HH];
__device__ float    g_ema_last[BB * HH];
__device__ unsigned g_cnt[NGRP * 32];       // per-group arrival counters (128B apart)

// ---------------- asm / math helpers -----------------------------------------
__device__ __forceinline__ unsigned ld_acq(const unsigned* p) {
    unsigned v;
    asm volatile("ld.acquire.gpu.global.u32 %0, [%1];" : "=r"(v) : "l"(p));
    return v;
}
__device__ __forceinline__ void red_add_release(unsigned* p, unsigned v) {
    asm volatile("red.release.gpu.global.add.u32 [%0], %1;" :: "l"(p), "r"(v) : "memory");
}
__device__ __forceinline__ float fsig(float x) {          // fast sigmoid
    return __fdividef(1.0f, 1.0f + __expf(-x));
}
__device__ __forceinline__ float ftanh(float x) {         // fast tanh
    return 1.0f - __fdividef(2.0f, __expf(2.0f * x) + 1.0f);
}
__device__ __forceinline__ unsigned long long dup2(float a) {
    unsigned long long r;
    asm("mov.b64 %0, {%1, %1};" : "=l"(r) : "f"(a));
    return r;
}
__device__ __forceinline__ void ffma2(unsigned long long& d,
                                      unsigned long long a, unsigned long long b) {
    asm("fma.rn.f32x2 %0, %1, %2, %0;" : "+l"(d) : "l"(a), "l"(b));
}
__device__ __forceinline__ void unpk(unsigned long long v, float& lo, float& hi) {
    asm("mov.b64 {%0, %1}, %2;" : "=f"(lo), "=f"(hi) : "l"(v));
}

// ---------------- prep: W_comb, fused bias, zero h(0), zero counters ---------
__global__ void __launch_bounds__(256)
prep_kernel(const float* __restrict__ W_in, const float* __restrict__ b_in,
            const float* __restrict__ W_ih, const float* __restrict__ b_ih,
            const float* __restrict__ b_hh)
{
    int idx = blockIdx.x * 256 + threadIdx.x;
    if (idx < NGRP * 32) g_cnt[idx] = 0u;
    if (idx < G4 * DIN) {
        int r = idx >> 5;          // gate row 0..1023
        int c = idx & 31;          // input col 0..31
        float s = 0.0f;
        for (int k = 0; k < HH; k++)
            s = fmaf(W_ih[r * HH + k], W_in[k * DIN + c], s);
        g_Wcomb[idx] = s;
        ((float*)g_h)[idx] = 0.0f;             // zero buffer 0 = h(0) (same 32768 extent)
    } else if (idx < G4 * DIN + G4) {
        int r = idx - G4 * DIN;
        float s = b_ih[r] + b_hh[r];
        for (int k = 0; k < HH; k++)
            s = fmaf(W_ih[r * HH + k], b_in[k], s);
        g_bias[r] = s;
    }
}

// ---------------- EMA: 64-step chunk -> (A, P) with out = A + P*prev ---------
__global__ void __launch_bounds__(256)
ema_scan_kernel(const float* __restrict__ x,
                const float* __restrict__ W_proj, const float* __restrict__ b_proj,
                const float* __restrict__ W_gate, const float* __restrict__ b_gate)
{
    const int b  = blockIdx.x >> 5;
    const int ch = blockIdx.x & 31;
    const int h  = threadIdx.x;

    __shared__ __align__(16) float x_s[64][DIN];
    for (int i = h; i < 64 * DIN; i += 256) {
        int tt = i >> 5, kk = i & 31;
        x_s[tt][kk] = x[((size_t)b * TT + ch * 64 + tt) * DIN + kk];
    }
    float wz[DIN], wg[DIN];
#pragma unroll
    for (int k = 0; k < DIN; k++) {
        wz[k] = W_proj[h * DIN + k];
        wg[k] = W_gate[h * DIN + k];
    }
    const float bz = b_proj[h], bgv = b_gate[h];
    __syncthreads();

    float A = 0.0f, P = 1.0f;
    for (int tt = 0; tt < 64; tt++) {
        float z = bz, gp = bgv;
#pragma unroll
        for (int q = 0; q < 8; q++) {
            float4 xq = *(const float4*)&x_s[tt][q * 4];
            z  = fmaf(wz[q*4+0], xq.x, z);  z  = fmaf(wz[q*4+1], xq.y, z);
            z  = fmaf(wz[q*4+2], xq.z, z);  z  = fmaf(wz[q*4+3], xq.w, z);
            gp = fmaf(wg[q*4+0], xq.x, gp); gp = fmaf(wg[q*4+1], xq.y, gp);
            gp = fmaf(wg[q*4+2], xq.z, gp); gp = fmaf(wg[q*4+3], xq.w, gp);
        }
        float g  = fsig(gp);
        float om = 1.0f - g;
        A = fmaf(om, A, g * z);
        P *= om;
    }
    g_emaA[((size_t)b * 32 + ch) * HH + h] = A;
    g_emaP[((size_t)b * 32 + ch) * HH + h] = P;
}

__global__ void __launch_bounds__(256) ema_combine_kernel()
{
    const int b = blockIdx.x;
    const int h = threadIdx.x;
    float prev = 0.0f;
#pragma unroll 8
    for (int c = 0; c < 32; c++) {
        float A = g_emaA[((size_t)b * 32 + c) * HH + h];
        float P = g_emaP[((size_t)b * 32 + c) * HH + h];
        prev = fmaf(P, prev, A);
    }
    g_ema_last[b * HH + h] = prev;
}

// ---------------- persistent LSTM recurrence --------------------------------
// 128 blocks = 16 batch-groups x 8 h-slices. Sync scope = 8 blocks of a group.
// Gate columns permuted: j = hc*4 + gi  (gate row r = gi*256 + n0 + hc), so the
// gate-phase reduction reads float4 quads.
// SMEM: W_s[288][128] (k-major), h_s[288][HS] staged h+x, red_s[64][128],
//       bias_s[128].
#define SMEM_FLOATS (KK*JPB + KK*HS + 64*JPB + JPB)
#define SMEM_BYTES  (SMEM_FLOATS * 4)

__global__ void __launch_bounds__(256, 1)
recur_kernel(const float* __restrict__ x, const float* __restrict__ W_hh)
{
    extern __shared__ float sm[];
    float* W_s    = sm;                        // [288][128]
    float* h_s    = W_s + KK * JPB;            // [288][HS]
    float* red_s  = h_s + KK * HS;             // [64][128]
    float* bias_s = red_s + 64 * JPB;          // [128]

    const int tid = threadIdx.x;
    const int bg  = blockIdx.x >> 3;
    const int m0  = bg * MPB;
    const int n0  = (blockIdx.x & 7) * NPB;

    // one-time: stage weight slice, col j = hc*4+gi -> gate row r = gi*256+n0+hc
    for (int idx = tid; idx < KK * JPB; idx += 256) {
        int k = idx >> 7;
        int j = idx & 127;
        int r = ((j & 3) << 8) + n0 + (j >> 2);
        W_s[idx] = (k < HH) ? W_hh[r * HH + k] : g_Wcomb[r * DIN + (k - HH)];
    }
    if (tid < JPB)
        bias_s[tid] = g_bias[((tid & 3) << 8) + n0 + (tid >> 2)];
    __syncthreads();

    const int m_ld = tid >> 5;      // staging: warp -> batch row
    const int k_ld = tid & 31;
    const int wid  = tid >> 5;
    const int lane = tid & 31;
    const int kbase = wid * 36;     // 8 warps * 36 = 288 = K
    const int mg = tid >> 5;        // gate-phase batch row
    const int hc = tid & 31;        // gate-phase h-col
    float c_val = 0.0f;
    const float4 bv = *(const float4*)&bias_s[hc * 4];   // bias quad (i,f,g,o)

    unsigned* cnt = &g_cnt[bg * 32];

    // h(0) zeros staged by prep_kernel (kernel-order visibility)
    for (int t = 0; t < TT; t++) {
        const int p = t & 1;
        // prefetch x_t (independent of recurrence)
        const float xv = __ldg(&x[((size_t)(m0 + m_ld) * TT + t) * DIN + k_ld]);

        // stage h(t) from L2 (written by peer SMs -> bypass L1) into h_s[k][m]
        {
            const float* hb = &g_h[p][m0 + m_ld][0];
#pragma unroll
            for (int q = 0; q < 8; q++)
                h_s[(k_ld + 32 * q) * HS + m_ld] = __ldcg(&hb[k_ld + 32 * q]);
            h_s[(HH + k_ld) * HS + m_ld] = xv;
        }
        __syncthreads();

        // K-split matvec, packed f32x2 over batch-row pairs:
        // warp wid covers k in [kbase, kbase+36)
        {
            unsigned long long acc2[4][4];     // [m-pair][c]
#pragma unroll
            for (int mp = 0; mp < 4; mp++)
#pragma unroll
                for (int c = 0; c < 4; c++) acc2[mp][c] = 0ull;

#pragma unroll 6
            for (int kk = 0; kk < 36; kk++) {
                const int k = kbase + kk;
                // h row: pairs (m0,m1)(m2,m3)(m4,m5)(m6,m7), each 8B-aligned
                const unsigned long long hp[4] = {
                    *(const unsigned long long*)&h_s[k * HS + 0],
                    *(const unsigned long long*)&h_s[k * HS + 2],
                    *(const unsigned long long*)&h_s[k * HS + 4],
                    *(const unsigned long long*)&h_s[k * HS + 6] };
                const float4 wv = *(const float4*)&W_s[k * JPB + lane * 4];
                const unsigned long long wd[4] =
                    { dup2(wv.x), dup2(wv.y), dup2(wv.z), dup2(wv.w) };
#pragma unroll
                for (int mp = 0; mp < 4; mp++) {
                    ffma2(acc2[mp][0], hp[mp], wd[0]);
                    ffma2(acc2[mp][1], hp[mp], wd[1]);
                    ffma2(acc2[mp][2], hp[mp], wd[2]);
                    ffma2(acc2[mp][3], hp[mp], wd[3]);
                }
            }

            float a[MPB][4];
#pragma unroll
            for (int mp = 0; mp < 4; mp++)
#pragma unroll
                for (int c = 0; c < 4; c++)
                    unpk(acc2[mp][c], a[2 * mp][c], a[2 * mp + 1][c]);
#pragma unroll
            for (int m = 0; m < MPB; m++)
                *(float4*)&red_s[(wid * MPB + m) * JPB + lane * 4] =
                    make_float4(a[m][0], a[m][1], a[m][2], a[m][3]);
        }
        __syncthreads();

        // gate phase: thread (mg, hc) reduces 8 k-partials as float4 quads
        {
            float4 sv = bv;
#pragma unroll
            for (int tk = 0; tk < 8; tk++) {
                const float4 r4 =
                    *(const float4*)&red_s[(tk * MPB + mg) * JPB + hc * 4];
                sv.x += r4.x; sv.y += r4.y; sv.z += r4.z; sv.w += r4.w;
            }
            const float ig = fsig(sv.x);
            const float fg = fsig(sv.y);
            const float gg = ftanh(sv.z);
            const float og = fsig(sv.w);
            c_val = fmaf(fg, c_val, ig * gg);
            g_h[p ^ 1][m0 + mg][n0 + hc] = og * ftanh(c_val);
        }

        // scoped group barrier: release-arrive by tid0, acquire-spin, no resets.
        __syncthreads();
        if (tid == 0) {
            red_add_release(cnt, 1u);
            const unsigned tgt = 8u * (unsigned)(t + 1);
            while (ld_acq(cnt) < tgt) { }
        }
        __syncthreads();
    }
    // h_last = h(2048) lives in g_h[0]
}

// ---------------- head: concat -> LayerNorm -> GELU(erf) MLP -> out ---------
__global__ void __launch_bounds__(256)
head_kernel(const float* __restrict__ ln_scale, const float* __restrict__ ln_bias,
            const float* __restrict__ W_h1, const float* __restrict__ b_h1,
            const float* __restrict__ W_h2, const float* __restrict__ b_h2,
            float* __restrict__ out)
{
    __shared__ __align__(16) float ns[512];
    __shared__ float red[32];
    __shared__ float mu_s, rv_s;

    const int b = blockIdx.x;
    const int tid = threadIdx.x;

    const float v0 = g_h[0][b][tid];
    const float v1 = g_ema_last[b * HH + tid];

    float s = v0 + v1, sq = v0 * v0 + v1 * v1;
#pragma unroll
    for (int o = 16; o; o >>= 1) {
        s  += __shfl_down_sync(0xffffffffu, s,  o);
        sq += __shfl_down_sync(0xffffffffu, sq, o);
    }
    if ((tid & 31) == 0) { red[tid >> 5] = s; red[8 + (tid >> 5)] = sq; }
    __syncthreads();
    if (tid == 0) {
        float ts = 0.f, tq = 0.f;
        for (int i = 0; i < 8; i++) { ts += red[i]; tq += red[8 + i]; }
        float mu = ts / 512.0f;
        mu_s = mu;
        rv_s = rsqrtf(tq / 512.0f - mu * mu + 1e-5f);
    }
    __syncthreads();
    const float mu = mu_s, ri = rv_s;
    ns[tid]       = fmaf((v0 - mu) * ri, ln_scale[tid],       ln_bias[tid]);
    ns[tid + 256] = fmaf((v1 - mu) * ri, ln_scale[tid + 256], ln_bias[tid + 256]);
    __syncthreads();

    float acc = b_h1[tid];
    const float4* wr = (const float4*)(W_h1 + (size_t)tid * 512);
#pragma unroll 8
    for (int q = 0; q < 128; q++) {
        float4 w = wr[q];
        float4 n = *(const float4*)&ns[q * 4];
        acc = fmaf(w.x, n.x, acc); acc = fmaf(w.y, n.y, acc);
        acc = fmaf(w.z, n.z, acc); acc = fmaf(w.w, n.w, acc);
    }
    float g1 = 0.5f * acc * (1.0f + erff(acc * 0.70710678118654752f));
    float p = g1 * W_h2[tid];
#pragma unroll
    for (int o = 16; o; o >>= 1) p += __shfl_down_sync(0xffffffffu, p, o);
    if ((tid & 31) == 0) red[16 + (tid >> 5)] = p;
    __syncthreads();
    if (tid == 0) {
        float tsum = b_h2[0];
        for (int i = 0; i < 8; i++) tsum += red[16 + i];
        out[b] = tsum;
    }
}

// ---------------- launch ----------------------------------------------------
extern "C" void kernel_launch(void* const* d_in, const int* in_sizes, int n_in,
                              void* d_out, int out_size)
{
    (void)in_sizes; (void)n_in; (void)out_size;
    const float* x        = (const float*)d_in[0];
    const float* W_in     = (const float*)d_in[1];
    const float* b_in     = (const float*)d_in[2];
    const float* W_ih     = (const float*)d_in[3];
    const float* W_hh     = (const float*)d_in[4];
    const float* b_ih     = (const float*)d_in[5];
    const float* b_hh     = (const float*)d_in[6];
    const float* W_proj   = (const float*)d_in[7];
    const float* b_proj   = (const float*)d_in[8];
    const float* W_gate   = (const float*)d_in[9];
    const float* b_gate   = (const float*)d_in[10];
    const float* ln_scale = (const float*)d_in[11];
    const float* ln_bias  = (const float*)d_in[12];
    const float* W_h1     = (const float*)d_in[13];
    const float* b_h1     = (const float*)d_in[14];
    const float* W_h2     = (const float*)d_in[15];
    const float* b_h2     = (const float*)d_in[16];
    float* out = (float*)d_out;

    cudaFuncSetAttribute(recur_kernel,
                         cudaFuncAttributeMaxDynamicSharedMemorySize, SMEM_BYTES);

    prep_kernel<<<132, 256>>>(W_in, b_in, W_ih, b_ih, b_hh);
    recur_kernel<<<NBLK, 256, SMEM_BYTES>>>(x, W_hh);
    ema_scan_kernel<<<BB * 32, 256>>>(x, W_proj, b_proj, W_gate, b_gate);
    ema_combine_kernel<<<BB, 256>>>();
    head_kernel<<<BB, 256>>>(ln_scale, ln_bias, W_h1, b_h1, W_h2, b_h2, out);
}

// round 9
// speedup vs baseline: 1.5830x; 1.1189x over previous
#include <cuda_runtime.h>
#include <math.h>

// Problem constants
#define BB    128
#define TT    2048
#define DIN   32
#define HH    256
#define G4    1024          // 4*H
#define KK    288           // H + DIN (input projection folded into recurrence)
#define NBLK  128           // persistent recurrence blocks (1/SM, co-resident)
#define MPB   8             // batch rows per block   (16 groups)
#define NPB   32            // h-cols per block       (8 slices)
#define JPB   128           // gate cols per block = 4*NPB
#define NGRP  16            // batch groups
#define HS    10            // h_s row stride (floats): 8B-aligned pairs
#define KPW   36            // k per warp (8 warps * 36 = 288)

// -------- static device scratch (no allocation allowed) --------
__device__ float    g_Wcomb[G4 * DIN];      // W_ih @ W_in   [1024][32]
__device__ float    g_bias[G4];             // b_ih + b_hh + W_ih @ b_in
__device__ float    g_h[2][BB][HH];         // double-buffered LSTM hidden state
__device__ float    g_emaA[BB * 32 * HH];
__device__ float    g_emaP[BB * 32 * HH];
__device__ float    g_ema_last[BB * HH];
__device__ unsigned g_cnt[NGRP * 32];       // per-group arrival counters (128B apart)

// ---------------- asm / math helpers -----------------------------------------
__device__ __forceinline__ unsigned ld_acq(const unsigned* p) {
    unsigned v;
    asm volatile("ld.acquire.gpu.global.u32 %0, [%1];" : "=r"(v) : "l"(p));
    return v;
}
__device__ __forceinline__ void red_add_release(unsigned* p, unsigned v) {
    asm volatile("red.release.gpu.global.add.u32 [%0], %1;" :: "l"(p), "r"(v) : "memory");
}
__device__ __forceinline__ float fsig(float x) {          // fast sigmoid
    return __fdividef(1.0f, 1.0f + __expf(-x));
}
__device__ __forceinline__ float ftanh(float x) {         // fast tanh
    return 1.0f - __fdividef(2.0f, __expf(2.0f * x) + 1.0f);
}
__device__ __forceinline__ unsigned long long dup2(float a) {
    unsigned long long r;
    asm("mov.b64 %0, {%1, %1};" : "=l"(r) : "f"(a));
    return r;
}
__device__ __forceinline__ void ffma2(unsigned long long& d,
                                      unsigned long long a, unsigned long long b) {
    asm("fma.rn.f32x2 %0, %1, %2, %0;" : "+l"(d) : "l"(a), "l"(b));
}
__device__ __forceinline__ void unpk(unsigned long long v, float& lo, float& hi) {
    asm("mov.b64 {%0, %1}, %2;" : "=f"(lo), "=f"(hi) : "l"(v));
}

// ---------------- prep: W_comb, fused bias, zero h(0), zero counters ---------
__global__ void __launch_bounds__(256)
prep_kernel(const float* __restrict__ W_in, const float* __restrict__ b_in,
            const float* __restrict__ W_ih, const float* __restrict__ b_ih,
            const float* __restrict__ b_hh)
{
    int idx = blockIdx.x * 256 + threadIdx.x;
    if (idx < NGRP * 32) g_cnt[idx] = 0u;
    if (idx < G4 * DIN) {
        int r = idx >> 5;          // gate row 0..1023
        int c = idx & 31;          // input col 0..31
        float s = 0.0f;
        for (int k = 0; k < HH; k++)
            s = fmaf(W_ih[r * HH + k], W_in[k * DIN + c], s);
        g_Wcomb[idx] = s;
        ((float*)g_h)[idx] = 0.0f;             // zero buffer 0 = h(0) (same 32768 extent)
    } else if (idx < G4 * DIN + G4) {
        int r = idx - G4 * DIN;
        float s = b_ih[r] + b_hh[r];
        for (int k = 0; k < HH; k++)
            s = fmaf(W_ih[r * HH + k], b_in[k], s);
        g_bias[r] = s;
    }
}

// ---------------- EMA: 64-step chunk -> (A, P) with out = A + P*prev ---------
__global__ void __launch_bounds__(256)
ema_scan_kernel(const float* __restrict__ x,
                const float* __restrict__ W_proj, const float* __restrict__ b_proj,
                const float* __restrict__ W_gate, const float* __restrict__ b_gate)
{
    const int b  = blockIdx.x >> 5;
    const int ch = blockIdx.x & 31;
    const int h  = threadIdx.x;

    __shared__ __align__(16) float x_s[64][DIN];
    for (int i = h; i < 64 * DIN; i += 256) {
        int tt = i >> 5, kk = i & 31;
        x_s[tt][kk] = x[((size_t)b * TT + ch * 64 + tt) * DIN + kk];
    }
    float wz[DIN], wg[DIN];
#pragma unroll
    for (int k = 0; k < DIN; k++) {
        wz[k] = W_proj[h * DIN + k];
        wg[k] = W_gate[h * DIN + k];
    }
    const float bz = b_proj[h], bgv = b_gate[h];
    __syncthreads();

    float A = 0.0f, P = 1.0f;
    for (int tt = 0; tt < 64; tt++) {
        float z = bz, gp = bgv;
#pragma unroll
        for (int q = 0; q < 8; q++) {
            float4 xq = *(const float4*)&x_s[tt][q * 4];
            z  = fmaf(wz[q*4+0], xq.x, z);  z  = fmaf(wz[q*4+1], xq.y, z);
            z  = fmaf(wz[q*4+2], xq.z, z);  z  = fmaf(wz[q*4+3], xq.w, z);
            gp = fmaf(wg[q*4+0], xq.x, gp); gp = fmaf(wg[q*4+1], xq.y, gp);
            gp = fmaf(wg[q*4+2], xq.z, gp); gp = fmaf(wg[q*4+3], xq.w, gp);
        }
        float g  = fsig(gp);
        float om = 1.0f - g;
        A = fmaf(om, A, g * z);
        P *= om;
    }
    g_emaA[((size_t)b * 32 + ch) * HH + h] = A;
    g_emaP[((size_t)b * 32 + ch) * HH + h] = P;
}

__global__ void __launch_bounds__(256) ema_combine_kernel()
{
    const int b = blockIdx.x;
    const int h = threadIdx.x;
    float prev = 0.0f;
#pragma unroll 8
    for (int c = 0; c < 32; c++) {
        float A = g_emaA[((size_t)b * 32 + c) * HH + h];
        float P = g_emaP[((size_t)b * 32 + c) * HH + h];
        prev = fmaf(P, prev, A);
    }
    g_ema_last[b * HH + h] = prev;
}

// ---------------- persistent LSTM recurrence --------------------------------
// 128 blocks = 16 batch-groups x 8 h-slices. Sync scope = 8 blocks of a group.
// Weights live in REGISTERS: thread (wid,lane) holds W rows {gi*256+n0+lane}
// for k in [wid*36, wid*36+36) as float4 wreg[36] (i,f,g,o per k).
// SMEM: h_s[288][HS] staged h+x, red_s[64][128].
#define SMEM_FLOATS (KK*HS + 64*JPB)
#define SMEM_BYTES  (SMEM_FLOATS * 4)

__global__ void __launch_bounds__(256, 1)
recur_kernel(const float* __restrict__ x, const float* __restrict__ W_hh)
{
    extern __shared__ float sm[];
    float* h_s    = sm;                        // [288][HS]
    float* red_s  = h_s + KK * HS;             // [64][128]

    const int tid = threadIdx.x;
    const int bg  = blockIdx.x >> 3;
    const int m0  = bg * MPB;
    const int n0  = (blockIdx.x & 7) * NPB;

    const int m_ld = tid >> 5;      // staging: warp -> batch row
    const int k_ld = tid & 31;
    const int wid  = tid >> 5;
    const int lane = tid & 31;
    const int kbase = wid * KPW;    // 8 warps * 36 = 288 = K
    const int mg = tid >> 5;        // gate-phase batch row
    const int hc = tid & 31;        // gate-phase h-col

    // one-time: load this thread's weight slice into registers.
    // wreg[kk] = (W[i-row][k], W[f-row][k], W[g-row][k], W[o-row][k]),
    // rows r(gi) = gi*256 + n0 + lane, k = kbase + kk.
    float4 wreg[KPW];
#pragma unroll
    for (int kk = 0; kk < KPW; kk++) {
        const int k = kbase + kk;
        float4 w;
        if (k < HH) {
            w.x = W_hh[(0 * 256 + n0 + lane) * HH + k];
            w.y = W_hh[(1 * 256 + n0 + lane) * HH + k];
            w.z = W_hh[(2 * 256 + n0 + lane) * HH + k];
            w.w = W_hh[(3 * 256 + n0 + lane) * HH + k];
        } else {
            const int kc = k - HH;
            w.x = g_Wcomb[(0 * 256 + n0 + lane) * DIN + kc];
            w.y = g_Wcomb[(1 * 256 + n0 + lane) * DIN + kc];
            w.z = g_Wcomb[(2 * 256 + n0 + lane) * DIN + kc];
            w.w = g_Wcomb[(3 * 256 + n0 + lane) * DIN + kc];
        }
        wreg[kk] = w;
    }
    // bias quad for gate phase (i,f,g,o at column n0+hc)
    const float4 bv = make_float4(g_bias[0 * 256 + n0 + hc],
                                  g_bias[1 * 256 + n0 + hc],
                                  g_bias[2 * 256 + n0 + hc],
                                  g_bias[3 * 256 + n0 + hc]);
    float c_val = 0.0f;

    unsigned* cnt = &g_cnt[bg * 32];

    // h(0) zeros staged by prep_kernel (kernel-order visibility)
    for (int t = 0; t < TT; t++) {
        const int p = t & 1;
        // prefetch x_t (independent of recurrence)
        const float xv = __ldg(&x[((size_t)(m0 + m_ld) * TT + t) * DIN + k_ld]);

        // stage h(t) from L2 (written by peer SMs -> bypass L1) into h_s[k][m]
        {
            const float* hb = &g_h[p][m0 + m_ld][0];
#pragma unroll
            for (int q = 0; q < 8; q++)
                h_s[(k_ld + 32 * q) * HS + m_ld] = __ldcg(&hb[k_ld + 32 * q]);
            h_s[(HH + k_ld) * HS + m_ld] = xv;
        }
        __syncthreads();

        // K-split matvec, f32x2 over batch-row pairs, W from registers.
        // h loads are warp-uniform (broadcast, conflict-free).
        {
            unsigned long long acc2[4][4];     // [m-pair][gate]
#pragma unroll
            for (int mp = 0; mp < 4; mp++)
#pragma unroll
                for (int c = 0; c < 4; c++) acc2[mp][c] = 0ull;

#pragma unroll
            for (int kk = 0; kk < KPW; kk++) {
                const int k = kbase + kk;
                const unsigned long long hp[4] = {
                    *(const unsigned long long*)&h_s[k * HS + 0],
                    *(const unsigned long long*)&h_s[k * HS + 2],
                    *(const unsigned long long*)&h_s[k * HS + 4],
                    *(const unsigned long long*)&h_s[k * HS + 6] };
                const float4 wv = wreg[kk];
                const unsigned long long wd[4] =
                    { dup2(wv.x), dup2(wv.y), dup2(wv.z), dup2(wv.w) };
#pragma unroll
                for (int mp = 0; mp < 4; mp++) {
                    ffma2(acc2[mp][0], hp[mp], wd[0]);
                    ffma2(acc2[mp][1], hp[mp], wd[1]);
                    ffma2(acc2[mp][2], hp[mp], wd[2]);
                    ffma2(acc2[mp][3], hp[mp], wd[3]);
                }
            }

            float a[MPB][4];
#pragma unroll
            for (int mp = 0; mp < 4; mp++)
#pragma unroll
                for (int c = 0; c < 4; c++)
                    unpk(acc2[mp][c], a[2 * mp][c], a[2 * mp + 1][c]);
#pragma unroll
            for (int m = 0; m < MPB; m++)
                *(float4*)&red_s[(wid * MPB + m) * JPB + lane * 4] =
                    make_float4(a[m][0], a[m][1], a[m][2], a[m][3]);
        }
        __syncthreads();

        // gate phase: thread (mg, hc) reduces 8 k-partials as float4 quads
        {
            float4 sv = bv;
#pragma unroll
            for (int tk = 0; tk < 8; tk++) {
                const float4 r4 =
                    *(const float4*)&red_s[(tk * MPB + mg) * JPB + hc * 4];
                sv.x += r4.x; sv.y += r4.y; sv.z += r4.z; sv.w += r4.w;
            }
            const float ig = fsig(sv.x);
            const float fg = fsig(sv.y);
            const float gg = ftanh(sv.z);
            const float og = fsig(sv.w);
            c_val = fmaf(fg, c_val, ig * gg);
            g_h[p ^ 1][m0 + mg][n0 + hc] = og * ftanh(c_val);
        }

        // scoped group barrier: release-arrive by tid0, acquire-spin, no resets.
        __syncthreads();
        if (tid == 0) {
            red_add_release(cnt, 1u);
            const unsigned tgt = 8u * (unsigned)(t + 1);
            while (ld_acq(cnt) < tgt) { }
        }
        __syncthreads();
    }
    // h_last = h(2048) lives in g_h[0]
}

// ---------------- head: concat -> LayerNorm -> GELU(erf) MLP -> out ---------
__global__ void __launch_bounds__(256)
head_kernel(const float* __restrict__ ln_scale, const float* __restrict__ ln_bias,
            const float* __restrict__ W_h1, const float* __restrict__ b_h1,
            const float* __restrict__ W_h2, const float* __restrict__ b_h2,
            float* __restrict__ out)
{
    __shared__ __align__(16) float ns[512];
    __shared__ float red[32];
    __shared__ float mu_s, rv_s;

    const int b = blockIdx.x;
    const int tid = threadIdx.x;

    const float v0 = g_h[0][b][tid];
    const float v1 = g_ema_last[b * HH + tid];

    float s = v0 + v1, sq = v0 * v0 + v1 * v1;
#pragma unroll
    for (int o = 16; o; o >>= 1) {
        s  += __shfl_down_sync(0xffffffffu, s,  o);
        sq += __shfl_down_sync(0xffffffffu, sq, o);
    }
    if ((tid & 31) == 0) { red[tid >> 5] = s; red[8 + (tid >> 5)] = sq; }
    __syncthreads();
    if (tid == 0) {
        float ts = 0.f, tq = 0.f;
        for (int i = 0; i < 8; i++) { ts += red[i]; tq += red[8 + i]; }
        float mu = ts / 512.0f;
        mu_s = mu;
        rv_s = rsqrtf(tq / 512.0f - mu * mu + 1e-5f);
    }
    __syncthreads();
    const float mu = mu_s, ri = rv_s;
    ns[tid]       = fmaf((v0 - mu) * ri, ln_scale[tid],       ln_bias[tid]);
    ns[tid + 256] = fmaf((v1 - mu) * ri, ln_scale[tid + 256], ln_bias[tid + 256]);
    __syncthreads();

    float acc = b_h1[tid];
    const float4* wr = (const float4*)(W_h1 + (size_t)tid * 512);
#pragma unroll 8
    for (int q = 0; q < 128; q++) {
        float4 w = wr[q];
        float4 n = *(const float4*)&ns[q * 4];
        acc = fmaf(w.x, n.x, acc); acc = fmaf(w.y, n.y, acc);
        acc = fmaf(w.z, n.z, acc); acc = fmaf(w.w, n.w, acc);
    }
    float g1 = 0.5f * acc * (1.0f + erff(acc * 0.70710678118654752f));
    float p = g1 * W_h2[tid];
#pragma unroll
    for (int o = 16; o; o >>= 1) p += __shfl_down_sync(0xffffffffu, p, o);
    if ((tid & 31) == 0) red[16 + (tid >> 5)] = p;
    __syncthreads();
    if (tid == 0) {
        float tsum = b_h2[0];
        for (int i = 0; i < 8; i++) tsum += red[16 + i];
        out[b] = tsum;
    }
}

// ---------------- launch ----------------------------------------------------
extern "C" void kernel_launch(void* const* d_in, const int* in_sizes, int n_in,
                              void* d_out, int out_size)
{
    (void)in_sizes; (void)n_in; (void)out_size;
    const float* x        = (const float*)d_in[0];
    const float* W_in     = (const float*)d_in[1];
    const float* b_in     = (const float*)d_in[2];
    const float* W_ih     = (const float*)d_in[3];
    const float* W_hh     = (const float*)d_in[4];
    const float* b_ih     = (const float*)d_in[5];
    const float* b_hh     = (const float*)d_in[6];
    const float* W_proj   = (const float*)d_in[7];
    const float* b_proj   = (const float*)d_in[8];
    const float* W_gate   = (const float*)d_in[9];
    const float* b_gate   = (const float*)d_in[10];
    const float* ln_scale = (const float*)d_in[11];
    const float* ln_bias  = (const float*)d_in[12];
    const float* W_h1     = (const float*)d_in[13];
    const float* b_h1     = (const float*)d_in[14];
    const float* W_h2     = (const float*)d_in[15];
    const float* b_h2     = (const float*)d_in[16];
    float* out = (float*)d_out;

    cudaFuncSetAttribute(recur_kernel,
                         cudaFuncAttributeMaxDynamicSharedMemorySize, SMEM_BYTES);

    prep_kernel<<<132, 256>>>(W_in, b_in, W_ih, b_ih, b_hh);
    recur_kernel<<<NBLK, 256, SMEM_BYTES>>>(x, W_hh);
    ema_scan_kernel<<<BB * 32, 256>>>(x, W_proj, b_proj, W_gate, b_gate);
    ema_combine_kernel<<<BB, 256>>>();
    head_kernel<<<BB, 256>>>(ln_scale, ln_bias, W_h1, b_h1, W_h2, b_h2, out);
}